// round 7
// baseline (speedup 1.0000x reference)
#include <cuda_runtime.h>

#define NN 2048
#define NE 65536
#define NVIEWS 6
#define C 32

typedef unsigned long long ull;

// ---- scratch. Invariant: g_agg == 0, g_cnt == 0 at entry of kernel_launch
// (zero-init at load; every consumer restores zeros). ----
__device__ float g_agg[NN * C];
__device__ int   g_cnt[NN];
__device__ float g_inv[NN];
__device__ float g_h1[NN * C];
__device__ float g_h2[NN * C];
__device__ float g_h3[NN * C];

// ---- f32x2 helpers ----
__device__ __forceinline__ ull pk(float lo, float hi) {
    ull r; asm("mov.b64 %0, {%1,%2};" : "=l"(r) : "f"(lo), "f"(hi)); return r;
}
__device__ __forceinline__ void upk(ull v, float& lo, float& hi) {
    asm("mov.b64 {%0,%1}, %2;" : "=f"(lo), "=f"(hi) : "l"(v));
}
__device__ __forceinline__ ull fma2(ull a, ull b, ull c) {
    ull d; asm("fma.rn.f32x2 %0,%1,%2,%3;" : "=l"(d) : "l"(a), "l"(b), "l"(c)); return d;
}
__device__ __forceinline__ ull add2(ull a, ull b) {
    ull d; asm("add.rn.f32x2 %0,%1,%2;" : "=l"(d) : "l"(a), "l"(b)); return d;
}

#define ABSMASK 0x7FFFFFFF7FFFFFFFULL

// ---- dummy first launch: keeps hot layer-3 edge_heavy at ncu capture index 5 ----
__global__ void warm_kernel() {}

// ---- layer 1 edge: in_c = 1. One warp per edge. Also counts degree. ----
__global__ void edge1_kernel(const float* __restrict__ x,
                             const int* __restrict__ ei,
                             const float* __restrict__ ea,
                             const float* __restrict__ W1,
                             const float* __restrict__ b1) {
    int gid  = blockIdx.x * blockDim.x + threadIdx.x;
    int e    = gid >> 5;
    int lane = gid & 31;
    if (e >= NE) return;
    float aval = (lane < NVIEWS) ? ea[e * NVIEWS + lane] : 0.f;
    int src = ei[e];
    int dst = ei[NE + e];
    float xs = __ldg(&x[src]);
    float wr = __ldg(&b1[lane]);
#pragma unroll
    for (int v = 0; v < NVIEWS; v++)
        wr = fmaf(__shfl_sync(0xffffffffu, aval, v), __ldg(&W1[v * C + lane]), wr);
    atomicAdd(&g_agg[dst * C + lane], xs * fmaxf(wr, 0.f));
    if (lane == 0) atomicAdd(&g_cnt[dst], 1);
}

// ---- node update 1 + stash inv + restore zeros ----
__global__ void node1_kernel(const float* __restrict__ x,
                             const float* __restrict__ root1,
                             const float* __restrict__ bias1) {
    int idx = blockIdx.x * blockDim.x + threadIdx.x;  // NN*C threads
    int n = idx >> 5, o = idx & 31;
    float inv = 1.f / fmaxf((float)g_cnt[n], 1.f);
    float v = fmaf(g_agg[idx], inv, fmaf(x[n], root1[o], bias1[o]));
    g_h1[idx] = fmaxf(v, 0.f);
    g_agg[idx] = 0.f;
    if (o == 0) { g_inv[n] = inv; g_cnt[n] = 0; }
}

// ---- heavy edge layer (in_c = 32). 256 threads = 8 warps, TE=8 edges/warp
// (NP=4 f32x2 pairs). lane = output channel o. W/bias DUPLICATED (w,w) as
// f32x2 in smem: one LDS.64 feeds fma2 directly. Gathered h pre-scaled by
// 0.5 so relu(w) = w + |w| folds into the chain.
// launch_bounds(256,3): cap regs ~85 -> 3 blocks/SM = 24 warps resident
// (R6 profile: 118 regs -> 2 blocks, issue stuck at 44%). ----
#define TE 8
#define NP 4
__global__ __launch_bounds__(256, 3)
void edge_heavy_kernel(int hin_sel,
                       const int* __restrict__ ei,
                       const float* __restrict__ ea,
                       const float* __restrict__ W,
                       const float* __restrict__ b) {
    __shared__ ull Wd[7 * 1024];        // rows 0..5 = W dup, row 6 = bias dup (56 KB)
    __shared__ ull hpp[8 * NP * 32];    // per-warp packed half-h pairs (8 KB)
    for (int i = threadIdx.x; i < 6 * 1024; i += 256) { float w = W[i]; Wd[i] = pk(w, w); }
    for (int i = threadIdx.x; i < 1024; i += 256)     { float w = b[i]; Wd[6 * 1024 + i] = pk(w, w); }
    __syncthreads();

    const float* __restrict__ h = (hin_sel == 1) ? g_h1 : g_h2;

    int lane = threadIdx.x & 31;
    int w    = threadIdx.x >> 5;
    int base = (blockIdx.x * 8 + w) * TE;

    // 48 contiguous edge_attr floats for 8 edges
    float av0 = ea[base * NVIEWS + lane];
    float av1 = (lane < 16) ? ea[base * NVIEWS + 32 + lane] : 0.f;

    ull a2[NP][NVIEWS];
#pragma unroll
    for (int p = 0; p < NP; p++)
#pragma unroll
        for (int v = 0; v < NVIEWS; v++) {
            const int f0 = (2 * p) * NVIEWS + v;
            const int f1 = f0 + NVIEWS;
            float x0 = (f0 < 32) ? __shfl_sync(0xffffffffu, av0, f0)
                                 : __shfl_sync(0xffffffffu, av1, f0 - 32);
            float x1 = (f1 < 32) ? __shfl_sync(0xffffffffu, av0, f1)
                                 : __shfl_sync(0xffffffffu, av1, f1 - 32);
            a2[p][v] = pk(x0, x1);
        }

    int srci = 0, dsti = 0;
    if (lane < TE) {
        srci = ei[base + lane];
        dsti = ei[NE + base + lane];
    }

    // gather h rows (pre-scaled by 0.5) for the 8 source nodes
#pragma unroll
    for (int p = 0; p < NP; p++) {
        int s0 = __shfl_sync(0xffffffffu, srci, 2 * p);
        int s1 = __shfl_sync(0xffffffffu, srci, 2 * p + 1);
        hpp[(w * NP + p) * 32 + lane] =
            pk(0.5f * h[s0 * C + lane], 0.5f * h[s1 * C + lane]);
    }
    __syncwarp();

    ull acc2[NP];
#pragma unroll
    for (int p = 0; p < NP; p++) acc2[p] = 0ull;

#pragma unroll 4
    for (int i = 0; i < C; i++) {
        ull wb  = Wd[6 * 1024 + (i << 5) + lane];
        ull wv0 = Wd[0 * 1024 + (i << 5) + lane];
        ull wv1 = Wd[1 * 1024 + (i << 5) + lane];
        ull wv2 = Wd[2 * 1024 + (i << 5) + lane];
        ull wv3 = Wd[3 * 1024 + (i << 5) + lane];
        ull wv4 = Wd[4 * 1024 + (i << 5) + lane];
        ull wv5 = Wd[5 * 1024 + (i << 5) + lane];
#pragma unroll
        for (int p = 0; p < NP; p++) {
            ull wr = wb;
            wr = fma2(a2[p][0], wv0, wr);
            wr = fma2(a2[p][1], wv1, wr);
            wr = fma2(a2[p][2], wv2, wr);
            wr = fma2(a2[p][3], wv3, wr);
            wr = fma2(a2[p][4], wv4, wr);
            wr = fma2(a2[p][5], wv5, wr);
            // relu folded: (wr + |wr|) * (0.5*h) ; h pre-scaled
            ull wrp = add2(wr, wr & ABSMASK);
            ull hh  = hpp[(w * NP + p) * 32 + i];
            acc2[p] = fma2(hh, wrp, acc2[p]);
        }
    }

#pragma unroll
    for (int p = 0; p < NP; p++) {
        int d0 = __shfl_sync(0xffffffffu, dsti, 2 * p);
        int d1 = __shfl_sync(0xffffffffu, dsti, 2 * p + 1);
        float lo, hi; upk(acc2[p], lo, hi);
        atomicAdd(&g_agg[d0 * C + lane], lo);
        atomicAdd(&g_agg[d1 * C + lane], hi);
    }
}

// ---- node update 2/3: warp per node, root via L1 (no smem/sync). ----
__global__ void nodeM_kernel(int sel,
                             const float* __restrict__ root,
                             const float* __restrict__ bias) {
    const float* __restrict__ hin = (sel == 1) ? g_h1 : g_h2;
    float* __restrict__ hout      = (sel == 1) ? g_h2 : g_h3;

    int warp = (blockIdx.x * blockDim.x + threadIdx.x) >> 5;
    int lane = threadIdx.x & 31;
    if (warp >= NN) return;
    int idx = warp * C + lane;
    float hval = hin[idx];
    float acc  = fmaf(g_agg[idx], g_inv[warp], __ldg(&bias[lane]));
    g_agg[idx] = 0.f;
#pragma unroll
    for (int i = 0; i < C; i++)
        acc = fmaf(__shfl_sync(0xffffffffu, hval, i),
                   __ldg(&root[(i << 5) + lane]), acc);
    hout[idx] = fmaxf(acc, 0.f);
}

// ---- CBT: all-pairs L1. Block tile 64(i) x 128(j); thread = 4i x 8j (4 ull).
// j interleave: thread (tx) handles j-pairs jp = tx + 16*jj (conflict-free,
// odd stride 63). ----
__global__ __launch_bounds__(256)
void cbt_kernel(float* __restrict__ out) {
    __shared__ ull hiD[64 * 32];   // [i][k] (v,v)            16 KB
    __shared__ ull hjN[64 * 63];   // [jp][k] (-h0,-h1)       31.5 KB
    int tid = threadIdx.x, lane = tid & 31, wrow = tid >> 5;
    int i0 = blockIdx.y * 64, j0 = blockIdx.x * 128;

    // load i-rows duplicated
#pragma unroll
    for (int r = 0; r < 8; r++) {
        int n = wrow * 8 + r;
        float v = g_h3[(i0 + n) * C + lane];
        hiD[n * 32 + lane] = pk(v, v);
    }
    // load j-rows negated into [jp][k] halves
    float* fj = (float*)hjN;
#pragma unroll
    for (int r = 0; r < 16; r++) {
        int n = wrow * 16 + r;            // 0..127
        float v = g_h3[(j0 + n) * C + lane];
        fj[2 * ((n >> 1) * 63 + lane) + (n & 1)] = -v;
    }
    __syncthreads();

    int tx = tid & 15;   // j base
    int ty = tid >> 4;   // i group
    ull acc2[4][4];
#pragma unroll
    for (int aa = 0; aa < 4; aa++)
#pragma unroll
        for (int jj = 0; jj < 4; jj++) acc2[aa][jj] = 0ull;

#pragma unroll 4
    for (int k = 0; k < C; k++) {
        ull aj[4];
#pragma unroll
        for (int jj = 0; jj < 4; jj++)
            aj[jj] = hjN[(tx + 16 * jj) * 63 + k];
#pragma unroll
        for (int aa = 0; aa < 4; aa++) {
            ull ai = hiD[(ty * 4 + aa) * 32 + k];
#pragma unroll
            for (int jj = 0; jj < 4; jj++) {
                ull d = add2(ai, aj[jj]) & ABSMASK;
                acc2[aa][jj] = add2(acc2[aa][jj], d);
            }
        }
    }
#pragma unroll
    for (int aa = 0; aa < 4; aa++) {
        size_t row = (size_t)(i0 + ty * 4 + aa) * NN;
#pragma unroll
        for (int jj = 0; jj < 4; jj++) {
            float lo, hi; upk(acc2[aa][jj], lo, hi);
            *(float2*)&out[row + j0 + 2 * (tx + 16 * jj)] = make_float2(lo, hi);
        }
    }
}

extern "C" void kernel_launch(void* const* d_in, const int* in_sizes, int n_in,
                              void* d_out, int out_size) {
    const float* x     = (const float*)d_in[0];
    const float* ea    = (const float*)d_in[1];
    const int*   ei    = (const int*)d_in[2];
    const float* W1    = (const float*)d_in[3];
    const float* b1    = (const float*)d_in[4];
    const float* root1 = (const float*)d_in[5];
    const float* bias1 = (const float*)d_in[6];
    const float* W2    = (const float*)d_in[7];
    const float* b2    = (const float*)d_in[8];
    const float* root2 = (const float*)d_in[9];
    const float* bias2 = (const float*)d_in[10];
    const float* W3    = (const float*)d_in[11];
    const float* b3    = (const float*)d_in[12];
    const float* root3 = (const float*)d_in[13];
    const float* bias3 = (const float*)d_in[14];
    float* out = (float*)d_out;

    const int EH_BLOCKS = NE / (8 * TE);   // 1024

    // idx 0 (keeps ncu -s 5 on layer-3 edge_heavy)
    warm_kernel<<<1, 32>>>();
    // idx 1,2
    edge1_kernel<<<(NE * 32) / 256, 256>>>(x, ei, ea, W1, b1);
    node1_kernel<<<(NN * C) / 256, 256>>>(x, root1, bias1);
    // layer 2: idx 3,4
    edge_heavy_kernel<<<EH_BLOCKS, 256>>>(1, ei, ea, W2, b2);
    nodeM_kernel<<<(NN * 32) / 256, 256>>>(1, root2, bias2);
    // layer 3: idx 5 (ncu capture), 6
    edge_heavy_kernel<<<EH_BLOCKS, 256>>>(2, ei, ea, W3, b3);
    nodeM_kernel<<<(NN * 32) / 256, 256>>>(2, root3, bias3);
    // CBT: idx 7
    cbt_kernel<<<dim3(NN / 128, NN / 64), 256>>>(out);
}

// round 8
// speedup vs baseline: 1.3924x; 1.3924x over previous
#include <cuda_runtime.h>

#define NN 2048
#define NE 65536
#define NVIEWS 6
#define C 32

typedef unsigned long long ull;

// ---- scratch. Invariant: g_agg == 0, g_cnt == 0 at entry of kernel_launch
// (zero-init at load; every consumer restores zeros). ----
__device__ float g_agg[NN * C];
__device__ int   g_cnt[NN];
__device__ float g_inv[NN];
__device__ float g_h1[NN * C];
__device__ float g_h2[NN * C];
__device__ float g_h3[NN * C];

// ---- f32x2 helpers ----
__device__ __forceinline__ ull pk(float lo, float hi) {
    ull r; asm("mov.b64 %0, {%1,%2};" : "=l"(r) : "f"(lo), "f"(hi)); return r;
}
__device__ __forceinline__ void upk(ull v, float& lo, float& hi) {
    asm("mov.b64 {%0,%1}, %2;" : "=f"(lo), "=f"(hi) : "l"(v));
}
__device__ __forceinline__ ull fma2(ull a, ull b, ull c) {
    ull d; asm("fma.rn.f32x2 %0,%1,%2,%3;" : "=l"(d) : "l"(a), "l"(b), "l"(c)); return d;
}
__device__ __forceinline__ ull add2(ull a, ull b) {
    ull d; asm("add.rn.f32x2 %0,%1,%2;" : "=l"(d) : "l"(a), "l"(b)); return d;
}

#define ABSMASK 0x7FFFFFFF7FFFFFFFULL

// ---- dummy first launch: keeps hot layer-3 edge_heavy at ncu capture index 5 ----
__global__ void warm_kernel() {}

// ---- layer 1 edge: in_c = 1. One warp per edge. Also counts degree. ----
__global__ void edge1_kernel(const float* __restrict__ x,
                             const int* __restrict__ ei,
                             const float* __restrict__ ea,
                             const float* __restrict__ W1,
                             const float* __restrict__ b1) {
    int gid  = blockIdx.x * blockDim.x + threadIdx.x;
    int e    = gid >> 5;
    int lane = gid & 31;
    if (e >= NE) return;
    float aval = (lane < NVIEWS) ? ea[e * NVIEWS + lane] : 0.f;
    int src = ei[e];
    int dst = ei[NE + e];
    float xs = __ldg(&x[src]);
    float wr = __ldg(&b1[lane]);
#pragma unroll
    for (int v = 0; v < NVIEWS; v++)
        wr = fmaf(__shfl_sync(0xffffffffu, aval, v), __ldg(&W1[v * C + lane]), wr);
    atomicAdd(&g_agg[dst * C + lane], xs * fmaxf(wr, 0.f));
    if (lane == 0) atomicAdd(&g_cnt[dst], 1);
}

// ---- node update 1 + stash inv + restore zeros ----
__global__ void node1_kernel(const float* __restrict__ x,
                             const float* __restrict__ root1,
                             const float* __restrict__ bias1) {
    int idx = blockIdx.x * blockDim.x + threadIdx.x;  // NN*C threads
    int n = idx >> 5, o = idx & 31;
    float inv = 1.f / fmaxf((float)g_cnt[n], 1.f);
    float v = fmaf(g_agg[idx], inv, fmaf(x[n], root1[o], bias1[o]));
    g_h1[idx] = fmaxf(v, 0.f);
    g_agg[idx] = 0.f;
    if (o == 0) { g_inv[n] = inv; g_cnt[n] = 0; }
}

// ---- heavy edge layer (in_c = 32). PERSISTENT: 296 blocks (2/SM), each
// loops over chunks of 64 edges; W/bias loaded into smem ONCE per block.
// 256 threads = 8 warps, TE=8 edges/warp (NP=4 f32x2 pairs). lane = output
// channel o. W/bias DUPLICATED (w,w) as f32x2 in smem: one LDS.64 feeds
// fma2 directly. Gathered h pre-scaled by 0.5 so relu(w) = w + |w| folds
// into the chain. No min-blocks clamp: R6's 118-reg / 2-block config is the
// proven optimum (R7 showed 80-reg cap -> spills -> 52us). ----
#define TE 8
#define NP 4
#define EH_GRID 296
#define EH_CHUNKS (NE / (8 * TE))   // 1024 chunks of 64 edges
__global__ __launch_bounds__(256)
void edge_heavy_kernel(int hin_sel,
                       const int* __restrict__ ei,
                       const float* __restrict__ ea,
                       const float* __restrict__ W,
                       const float* __restrict__ b) {
    __shared__ ull Wd[7 * 1024];        // rows 0..5 = W dup, row 6 = bias dup (56 KB)
    __shared__ ull hpp[8 * NP * 32];    // per-warp packed half-h pairs (8 KB)
    for (int i = threadIdx.x; i < 6 * 1024; i += 256) { float w = W[i]; Wd[i] = pk(w, w); }
    for (int i = threadIdx.x; i < 1024; i += 256)     { float w = b[i]; Wd[6 * 1024 + i] = pk(w, w); }
    __syncthreads();

    const float* __restrict__ h = (hin_sel == 1) ? g_h1 : g_h2;

    int lane = threadIdx.x & 31;
    int w    = threadIdx.x >> 5;

    for (int chunk = blockIdx.x; chunk < EH_CHUNKS; chunk += EH_GRID) {
        int base = (chunk * 8 + w) * TE;

        // 48 contiguous edge_attr floats for 8 edges
        float av0 = ea[base * NVIEWS + lane];
        float av1 = (lane < 16) ? ea[base * NVIEWS + 32 + lane] : 0.f;

        ull a2[NP][NVIEWS];
#pragma unroll
        for (int p = 0; p < NP; p++)
#pragma unroll
            for (int v = 0; v < NVIEWS; v++) {
                const int f0 = (2 * p) * NVIEWS + v;
                const int f1 = f0 + NVIEWS;
                float x0 = (f0 < 32) ? __shfl_sync(0xffffffffu, av0, f0)
                                     : __shfl_sync(0xffffffffu, av1, f0 - 32);
                float x1 = (f1 < 32) ? __shfl_sync(0xffffffffu, av0, f1)
                                     : __shfl_sync(0xffffffffu, av1, f1 - 32);
                a2[p][v] = pk(x0, x1);
            }

        int srci = 0, dsti = 0;
        if (lane < TE) {
            srci = ei[base + lane];
            dsti = ei[NE + base + lane];
        }

        // gather h rows (pre-scaled by 0.5) for the 8 source nodes
#pragma unroll
        for (int p = 0; p < NP; p++) {
            int s0 = __shfl_sync(0xffffffffu, srci, 2 * p);
            int s1 = __shfl_sync(0xffffffffu, srci, 2 * p + 1);
            hpp[(w * NP + p) * 32 + lane] =
                pk(0.5f * h[s0 * C + lane], 0.5f * h[s1 * C + lane]);
        }
        __syncwarp();

        ull acc2[NP];
#pragma unroll
        for (int p = 0; p < NP; p++) acc2[p] = 0ull;

#pragma unroll 8
        for (int i = 0; i < C; i++) {
            ull wb  = Wd[6 * 1024 + (i << 5) + lane];
            ull wv0 = Wd[0 * 1024 + (i << 5) + lane];
            ull wv1 = Wd[1 * 1024 + (i << 5) + lane];
            ull wv2 = Wd[2 * 1024 + (i << 5) + lane];
            ull wv3 = Wd[3 * 1024 + (i << 5) + lane];
            ull wv4 = Wd[4 * 1024 + (i << 5) + lane];
            ull wv5 = Wd[5 * 1024 + (i << 5) + lane];
#pragma unroll
            for (int p = 0; p < NP; p++) {
                ull wr = wb;
                wr = fma2(a2[p][0], wv0, wr);
                wr = fma2(a2[p][1], wv1, wr);
                wr = fma2(a2[p][2], wv2, wr);
                wr = fma2(a2[p][3], wv3, wr);
                wr = fma2(a2[p][4], wv4, wr);
                wr = fma2(a2[p][5], wv5, wr);
                // relu folded: (wr + |wr|) * (0.5*h) ; h pre-scaled
                ull wrp = add2(wr, wr & ABSMASK);
                ull hh  = hpp[(w * NP + p) * 32 + i];
                acc2[p] = fma2(hh, wrp, acc2[p]);
            }
        }

#pragma unroll
        for (int p = 0; p < NP; p++) {
            int d0 = __shfl_sync(0xffffffffu, dsti, 2 * p);
            int d1 = __shfl_sync(0xffffffffu, dsti, 2 * p + 1);
            float lo, hi; upk(acc2[p], lo, hi);
            atomicAdd(&g_agg[d0 * C + lane], lo);
            atomicAdd(&g_agg[d1 * C + lane], hi);
        }
        __syncwarp();
    }
}

// ---- node update 2/3: warp per node, root via L1 (no smem/sync). ----
__global__ void nodeM_kernel(int sel,
                             const float* __restrict__ root,
                             const float* __restrict__ bias) {
    const float* __restrict__ hin = (sel == 1) ? g_h1 : g_h2;
    float* __restrict__ hout      = (sel == 1) ? g_h2 : g_h3;

    int warp = (blockIdx.x * blockDim.x + threadIdx.x) >> 5;
    int lane = threadIdx.x & 31;
    if (warp >= NN) return;
    int idx = warp * C + lane;
    float hval = hin[idx];
    float acc  = fmaf(g_agg[idx], g_inv[warp], __ldg(&bias[lane]));
    g_agg[idx] = 0.f;
#pragma unroll
    for (int i = 0; i < C; i++)
        acc = fmaf(__shfl_sync(0xffffffffu, hval, i),
                   __ldg(&root[(i << 5) + lane]), acc);
    hout[idx] = fmaxf(acc, 0.f);
}

// ---- CBT: all-pairs L1. Block tile 64(i) x 128(j); thread = 4i x 8j (4 ull).
// j interleave: thread (tx) handles j-pairs jp = tx + 16*jj (conflict-free,
// odd stride 63). ----
__global__ __launch_bounds__(256)
void cbt_kernel(float* __restrict__ out) {
    __shared__ ull hiD[64 * 32];   // [i][k] (v,v)            16 KB
    __shared__ ull hjN[64 * 63];   // [jp][k] (-h0,-h1)       31.5 KB
    int tid = threadIdx.x, lane = tid & 31, wrow = tid >> 5;
    int i0 = blockIdx.y * 64, j0 = blockIdx.x * 128;

    // load i-rows duplicated
#pragma unroll
    for (int r = 0; r < 8; r++) {
        int n = wrow * 8 + r;
        float v = g_h3[(i0 + n) * C + lane];
        hiD[n * 32 + lane] = pk(v, v);
    }
    // load j-rows negated into [jp][k] halves
    float* fj = (float*)hjN;
#pragma unroll
    for (int r = 0; r < 16; r++) {
        int n = wrow * 16 + r;            // 0..127
        float v = g_h3[(j0 + n) * C + lane];
        fj[2 * ((n >> 1) * 63 + lane) + (n & 1)] = -v;
    }
    __syncthreads();

    int tx = tid & 15;   // j base
    int ty = tid >> 4;   // i group
    ull acc2[4][4];
#pragma unroll
    for (int aa = 0; aa < 4; aa++)
#pragma unroll
        for (int jj = 0; jj < 4; jj++) acc2[aa][jj] = 0ull;

#pragma unroll 4
    for (int k = 0; k < C; k++) {
        ull aj[4];
#pragma unroll
        for (int jj = 0; jj < 4; jj++)
            aj[jj] = hjN[(tx + 16 * jj) * 63 + k];
#pragma unroll
        for (int aa = 0; aa < 4; aa++) {
            ull ai = hiD[(ty * 4 + aa) * 32 + k];
#pragma unroll
            for (int jj = 0; jj < 4; jj++) {
                ull d = add2(ai, aj[jj]) & ABSMASK;
                acc2[aa][jj] = add2(acc2[aa][jj], d);
            }
        }
    }
#pragma unroll
    for (int aa = 0; aa < 4; aa++) {
        size_t row = (size_t)(i0 + ty * 4 + aa) * NN;
#pragma unroll
        for (int jj = 0; jj < 4; jj++) {
            float lo, hi; upk(acc2[aa][jj], lo, hi);
            *(float2*)&out[row + j0 + 2 * (tx + 16 * jj)] = make_float2(lo, hi);
        }
    }
}

extern "C" void kernel_launch(void* const* d_in, const int* in_sizes, int n_in,
                              void* d_out, int out_size) {
    const float* x     = (const float*)d_in[0];
    const float* ea    = (const float*)d_in[1];
    const int*   ei    = (const int*)d_in[2];
    const float* W1    = (const float*)d_in[3];
    const float* b1    = (const float*)d_in[4];
    const float* root1 = (const float*)d_in[5];
    const float* bias1 = (const float*)d_in[6];
    const float* W2    = (const float*)d_in[7];
    const float* b2    = (const float*)d_in[8];
    const float* root2 = (const float*)d_in[9];
    const float* bias2 = (const float*)d_in[10];
    const float* W3    = (const float*)d_in[11];
    const float* b3    = (const float*)d_in[12];
    const float* root3 = (const float*)d_in[13];
    const float* bias3 = (const float*)d_in[14];
    float* out = (float*)d_out;

    // idx 0 (keeps ncu -s 5 on layer-3 edge_heavy)
    warm_kernel<<<1, 32>>>();
    // idx 1,2
    edge1_kernel<<<(NE * 32) / 256, 256>>>(x, ei, ea, W1, b1);
    node1_kernel<<<(NN * C) / 256, 256>>>(x, root1, bias1);
    // layer 2: idx 3,4
    edge_heavy_kernel<<<EH_GRID, 256>>>(1, ei, ea, W2, b2);
    nodeM_kernel<<<(NN * 32) / 256, 256>>>(1, root2, bias2);
    // layer 3: idx 5 (ncu capture), 6
    edge_heavy_kernel<<<EH_GRID, 256>>>(2, ei, ea, W3, b3);
    nodeM_kernel<<<(NN * 32) / 256, 256>>>(2, root3, bias3);
    // CBT: idx 7
    cbt_kernel<<<dim3(NN / 128, NN / 64), 256>>>(out);
}

// round 10
// speedup vs baseline: 1.4532x; 1.0437x over previous
#include <cuda_runtime.h>

#define NN 2048
#define NE 65536
#define NVIEWS 6
#define C 32

typedef unsigned long long ull;

// ---- scratch. Invariant: g_agg == 0, g_cnt == 0 at entry of kernel_launch
// (zero-init at load; every consumer restores zeros). ----
__device__ float g_agg[NN * C];
__device__ int   g_cnt[NN];
__device__ float g_inv[NN];
__device__ float g_h1[NN * C];
__device__ float g_h2[NN * C];
__device__ float g_h3[NN * C];

// ---- f32x2 helpers ----
__device__ __forceinline__ ull pk(float lo, float hi) {
    ull r; asm("mov.b64 %0, {%1,%2};" : "=l"(r) : "f"(lo), "f"(hi)); return r;
}
__device__ __forceinline__ void upk(ull v, float& lo, float& hi) {
    asm("mov.b64 {%0,%1}, %2;" : "=f"(lo), "=f"(hi) : "l"(v));
}
__device__ __forceinline__ ull fma2(ull a, ull b, ull c) {
    ull d; asm("fma.rn.f32x2 %0,%1,%2,%3;" : "=l"(d) : "l"(a), "l"(b), "l"(c)); return d;
}
__device__ __forceinline__ ull add2(ull a, ull b) {
    ull d; asm("add.rn.f32x2 %0,%1,%2;" : "=l"(d) : "l"(a), "l"(b)); return d;
}

#define ABSMASK 0x7FFFFFFF7FFFFFFFULL

// ---- dummy first launch: keeps hot layer-3 edge_heavy at ncu capture index 5 ----
__global__ void warm_kernel() {}

// ---- layer 1 edge: in_c = 1. One warp per edge. Also counts degree. ----
__global__ void edge1_kernel(const float* __restrict__ x,
                             const int* __restrict__ ei,
                             const float* __restrict__ ea,
                             const float* __restrict__ W1,
                             const float* __restrict__ b1) {
    int gid  = blockIdx.x * blockDim.x + threadIdx.x;
    int e    = gid >> 5;
    int lane = gid & 31;
    if (e >= NE) return;
    float aval = (lane < NVIEWS) ? ea[e * NVIEWS + lane] : 0.f;
    int src = ei[e];
    int dst = ei[NE + e];
    float xs = __ldg(&x[src]);
    float wr = __ldg(&b1[lane]);
#pragma unroll
    for (int v = 0; v < NVIEWS; v++)
        wr = fmaf(__shfl_sync(0xffffffffu, aval, v), __ldg(&W1[v * C + lane]), wr);
    atomicAdd(&g_agg[dst * C + lane], xs * fmaxf(wr, 0.f));
    if (lane == 0) atomicAdd(&g_cnt[dst], 1);
}

// ---- node update 1 + stash inv + restore zeros ----
__global__ void node1_kernel(const float* __restrict__ x,
                             const float* __restrict__ root1,
                             const float* __restrict__ bias1) {
    int idx = blockIdx.x * blockDim.x + threadIdx.x;  // NN*C threads
    int n = idx >> 5, o = idx & 31;
    float inv = 1.f / fmaxf((float)g_cnt[n], 1.f);
    float v = fmaf(g_agg[idx], inv, fmaf(x[n], root1[o], bias1[o]));
    g_h1[idx] = fmaxf(v, 0.f);
    g_agg[idx] = 0.f;
    if (o == 0) { g_inv[n] = inv; g_cnt[n] = 0; }
}

// ---- heavy edge layer (in_c = 32). PERSISTENT: 296 blocks (2/SM), chunks
// of 64 edges; W/bias in smem ONCE per block, DUPLICATED (w,w) f32x2 with
// TWO consecutive i-channels adjacent -> LDS.128 feeds 2 i-iterations.
// 8 warps, TE=8 edges/warp (NP=4 pairs), lane = output channel.
// relu folded: (wr + |wr|) * (0.5*h), h pre-scaled. ----
#define TE 8
#define NP 4
#define EH_GRID 296
#define EH_CHUNKS (NE / (8 * TE))   // 1024 chunks of 64 edges
// Wd layout (ull units): W [v][ip][lane][sub] idx = (((v*16+ip)*32)+lane)*2+sub
// bias at 6144 + ((ip*32)+lane)*2 + sub.  16 ip = 32 i-channels.
#define WD_ULL (7 * 1024)
__global__ __launch_bounds__(256, 2)
void edge_heavy_kernel(int hin_sel,
                       const int* __restrict__ ei,
                       const float* __restrict__ ea,
                       const float* __restrict__ W,
                       const float* __restrict__ b) {
    __shared__ __align__(16) ull Wd[WD_ULL];       // 56 KB
    __shared__ __align__(16) ull hpp[8 * NP * 32]; // 8 KB
    for (int idx = threadIdx.x; idx < 6 * 1024; idx += 256) {
        int v = idx >> 10, rem = idx & 1023, i = rem >> 5, o = rem & 31;
        float w = W[idx];
        Wd[((((v << 4) + (i >> 1)) << 5) + o) * 2 + (i & 1)] = pk(w, w);
    }
    for (int idx = threadIdx.x; idx < 1024; idx += 256) {
        int i = idx >> 5, o = idx & 31;
        float w = b[idx];
        Wd[6144 + ((((i >> 1) << 5) + o) << 1) + (i & 1)] = pk(w, w);
    }
    __syncthreads();

    const float* __restrict__ h = (hin_sel == 1) ? g_h1 : g_h2;

    int lane = threadIdx.x & 31;
    int w    = threadIdx.x >> 5;

    for (int chunk = blockIdx.x; chunk < EH_CHUNKS; chunk += EH_GRID) {
        int base = (chunk * 8 + w) * TE;

        // 48 contiguous edge_attr floats for 8 edges
        float av0 = ea[base * NVIEWS + lane];
        float av1 = (lane < 16) ? ea[base * NVIEWS + 32 + lane] : 0.f;

        ull a2[NP][NVIEWS];
#pragma unroll
        for (int p = 0; p < NP; p++)
#pragma unroll
            for (int v = 0; v < NVIEWS; v++) {
                const int f0 = (2 * p) * NVIEWS + v;
                const int f1 = f0 + NVIEWS;
                float x0 = (f0 < 32) ? __shfl_sync(0xffffffffu, av0, f0)
                                     : __shfl_sync(0xffffffffu, av1, f0 - 32);
                float x1 = (f1 < 32) ? __shfl_sync(0xffffffffu, av0, f1)
                                     : __shfl_sync(0xffffffffu, av1, f1 - 32);
                a2[p][v] = pk(x0, x1);
            }

        int srci = 0, dsti = 0;
        if (lane < TE) {
            srci = ei[base + lane];
            dsti = ei[NE + base + lane];
        }

        // gather h rows (pre-scaled by 0.5) for the 8 source nodes
#pragma unroll
        for (int p = 0; p < NP; p++) {
            int s0 = __shfl_sync(0xffffffffu, srci, 2 * p);
            int s1 = __shfl_sync(0xffffffffu, srci, 2 * p + 1);
            hpp[(w * NP + p) * 32 + lane] =
                pk(0.5f * h[s0 * C + lane], 0.5f * h[s1 * C + lane]);
        }
        __syncwarp();

        ull acc2[NP];
#pragma unroll
        for (int p = 0; p < NP; p++) acc2[p] = 0ull;

#pragma unroll 2
        for (int ip = 0; ip < 16; ip++) {
            int l2 = lane << 1;
            ulonglong2 wb  = *(const ulonglong2*)&Wd[6144 + (ip << 6) + l2];
            ulonglong2 wv0 = *(const ulonglong2*)&Wd[(((0 << 4) + ip) << 6) + l2];
            ulonglong2 wv1 = *(const ulonglong2*)&Wd[(((1 << 4) + ip) << 6) + l2];
            ulonglong2 wv2 = *(const ulonglong2*)&Wd[(((2 << 4) + ip) << 6) + l2];
            ulonglong2 wv3 = *(const ulonglong2*)&Wd[(((3 << 4) + ip) << 6) + l2];
            ulonglong2 wv4 = *(const ulonglong2*)&Wd[(((4 << 4) + ip) << 6) + l2];
            ulonglong2 wv5 = *(const ulonglong2*)&Wd[(((5 << 4) + ip) << 6) + l2];
#pragma unroll
            for (int p = 0; p < NP; p++) {
                ulonglong2 hh = *(const ulonglong2*)&hpp[(w * NP + p) * 32 + (ip << 1)];
                ull wrA = wb.x;
                wrA = fma2(a2[p][0], wv0.x, wrA);
                wrA = fma2(a2[p][1], wv1.x, wrA);
                wrA = fma2(a2[p][2], wv2.x, wrA);
                wrA = fma2(a2[p][3], wv3.x, wrA);
                wrA = fma2(a2[p][4], wv4.x, wrA);
                wrA = fma2(a2[p][5], wv5.x, wrA);
                ull wrB = wb.y;
                wrB = fma2(a2[p][0], wv0.y, wrB);
                wrB = fma2(a2[p][1], wv1.y, wrB);
                wrB = fma2(a2[p][2], wv2.y, wrB);
                wrB = fma2(a2[p][3], wv3.y, wrB);
                wrB = fma2(a2[p][4], wv4.y, wrB);
                wrB = fma2(a2[p][5], wv5.y, wrB);
                // relu folded: (wr + |wr|) * (0.5*h)
                acc2[p] = fma2(hh.x, add2(wrA, wrA & ABSMASK), acc2[p]);
                acc2[p] = fma2(hh.y, add2(wrB, wrB & ABSMASK), acc2[p]);
            }
        }

#pragma unroll
        for (int p = 0; p < NP; p++) {
            int d0 = __shfl_sync(0xffffffffu, dsti, 2 * p);
            int d1 = __shfl_sync(0xffffffffu, dsti, 2 * p + 1);
            float lo, hi; upk(acc2[p], lo, hi);
            atomicAdd(&g_agg[d0 * C + lane], lo);
            atomicAdd(&g_agg[d1 * C + lane], hi);
        }
        __syncwarp();
    }
}

// ---- node update 2/3: warp per node, root via L1 (no smem/sync). ----
__global__ void nodeM_kernel(int sel,
                             const float* __restrict__ root,
                             const float* __restrict__ bias) {
    const float* __restrict__ hin = (sel == 1) ? g_h1 : g_h2;
    float* __restrict__ hout      = (sel == 1) ? g_h2 : g_h3;

    int warp = (blockIdx.x * blockDim.x + threadIdx.x) >> 5;
    int lane = threadIdx.x & 31;
    if (warp >= NN) return;
    int idx = warp * C + lane;
    float hval = hin[idx];
    float acc  = fmaf(g_agg[idx], g_inv[warp], __ldg(&bias[lane]));
    g_agg[idx] = 0.f;
#pragma unroll
    for (int i = 0; i < C; i++)
        acc = fmaf(__shfl_sync(0xffffffffu, hval, i),
                   __ldg(&root[(i << 5) + lane]), acc);
    hout[idx] = fmaxf(acc, 0.f);
}

// ---- CBT: all-pairs L1. Block tile 64(i) x 128(j); thread = 4i x 8j.
// smem row stride 34 ull (17 ulonglong2) -> LDS.128 loads 2 k's per instr,
// 16B-aligned, conflict-light. ----
__global__ __launch_bounds__(256)
void cbt_kernel(float* __restrict__ out) {
    __shared__ __align__(16) ull hiD[64 * 34];   // [i][k] (v,v)      17 KB
    __shared__ __align__(16) ull hjN[64 * 34];   // [jp][k] (-h0,-h1) 17 KB
    int tid = threadIdx.x, lane = tid & 31, wrow = tid >> 5;
    int i0 = blockIdx.y * 64, j0 = blockIdx.x * 128;

    // load i-rows duplicated
#pragma unroll
    for (int r = 0; r < 8; r++) {
        int n = wrow * 8 + r;
        float v = g_h3[(i0 + n) * C + lane];
        hiD[n * 34 + lane] = pk(v, v);
    }
    // load j-rows negated into [jp][k] halves
    float* fj = (float*)hjN;
#pragma unroll
    for (int r = 0; r < 16; r++) {
        int n = wrow * 16 + r;            // 0..127
        float v = g_h3[(j0 + n) * C + lane];
        fj[2 * ((n >> 1) * 34 + lane) + (n & 1)] = -v;
    }
    __syncthreads();

    int tx = tid & 15;   // j base
    int ty = tid >> 4;   // i group
    ull acc2[4][4];
#pragma unroll
    for (int aa = 0; aa < 4; aa++)
#pragma unroll
        for (int jj = 0; jj < 4; jj++) acc2[aa][jj] = 0ull;

#pragma unroll 4
    for (int kp = 0; kp < 16; kp++) {
        ulonglong2 aj[4];
#pragma unroll
        for (int jj = 0; jj < 4; jj++)
            aj[jj] = *(const ulonglong2*)&hjN[(tx + 16 * jj) * 34 + 2 * kp];
#pragma unroll
        for (int aa = 0; aa < 4; aa++) {
            ulonglong2 ai = *(const ulonglong2*)&hiD[(ty * 4 + aa) * 34 + 2 * kp];
#pragma unroll
            for (int jj = 0; jj < 4; jj++) {
                ull d0 = add2(ai.x, aj[jj].x) & ABSMASK;
                acc2[aa][jj] = add2(acc2[aa][jj], d0);
                ull d1 = add2(ai.y, aj[jj].y) & ABSMASK;
                acc2[aa][jj] = add2(acc2[aa][jj], d1);
            }
        }
    }
#pragma unroll
    for (int aa = 0; aa < 4; aa++) {
        size_t row = (size_t)(i0 + ty * 4 + aa) * NN;
#pragma unroll
        for (int jj = 0; jj < 4; jj++) {
            float lo, hi; upk(acc2[aa][jj], lo, hi);
            *(float2*)&out[row + j0 + 2 * (tx + 16 * jj)] = make_float2(lo, hi);
        }
    }
}

extern "C" void kernel_launch(void* const* d_in, const int* in_sizes, int n_in,
                              void* d_out, int out_size) {
    const float* x     = (const float*)d_in[0];
    const float* ea    = (const float*)d_in[1];
    const int*   ei    = (const int*)d_in[2];
    const float* W1    = (const float*)d_in[3];
    const float* b1    = (const float*)d_in[4];
    const float* root1 = (const float*)d_in[5];
    const float* bias1 = (const float*)d_in[6];
    const float* W2    = (const float*)d_in[7];
    const float* b2    = (const float*)d_in[8];
    const float* root2 = (const float*)d_in[9];
    const float* bias2 = (const float*)d_in[10];
    const float* W3    = (const float*)d_in[11];
    const float* b3    = (const float*)d_in[12];
    const float* root3 = (const float*)d_in[13];
    const float* bias3 = (const float*)d_in[14];
    float* out = (float*)d_out;

    // idx 0 (keeps ncu -s 5 on layer-3 edge_heavy)
    warm_kernel<<<1, 32>>>();
    // idx 1,2
    edge1_kernel<<<(NE * 32) / 256, 256>>>(x, ei, ea, W1, b1);
    node1_kernel<<<(NN * C) / 256, 256>>>(x, root1, bias1);
    // layer 2: idx 3,4
    edge_heavy_kernel<<<EH_GRID, 256>>>(1, ei, ea, W2, b2);
    nodeM_kernel<<<(NN * 32) / 256, 256>>>(1, root2, bias2);
    // layer 3: idx 5 (ncu capture), 6
    edge_heavy_kernel<<<EH_GRID, 256>>>(2, ei, ea, W3, b3);
    nodeM_kernel<<<(NN * 32) / 256, 256>>>(2, root3, bias3);
    // CBT: idx 7
    cbt_kernel<<<dim3(NN / 128, NN / 64), 256>>>(out);
}